// round 1
// baseline (speedup 1.0000x reference)
#include <cuda_runtime.h>

#define BATCH 32
#define SLEN  1024
#define EDIM  512
#define UDIM  512
#define DDIM  512

#define BM 64
#define BN 64
#define BK 32
#define KTILES (EDIM / BK)   // 16
#define NTILES (UDIM / BN)   // 8

// Scratch (no allocations allowed in kernel_launch)
__device__ float g_dec_proj[BATCH * UDIM];
__device__ float g_scores[BATCH * SLEN];   // scores, then alpha in-place

// ---------------- f32x2 packed helpers (full-rate fp32 on Blackwell) --------
__device__ __forceinline__ unsigned long long pack2(float lo, float hi) {
    unsigned long long r;
    asm("mov.b64 %0, {%1, %2};" : "=l"(r) : "f"(lo), "f"(hi));
    return r;
}
__device__ __forceinline__ void unpack2(unsigned long long v, float& lo, float& hi) {
    asm("mov.b64 {%0, %1}, %2;" : "=f"(lo), "=f"(hi) : "l"(v));
}
__device__ __forceinline__ void fma2(unsigned long long& d, unsigned long long a,
                                     unsigned long long b) {
    asm("fma.rn.f32x2 %0, %1, %2, %0;" : "+l"(d) : "l"(a), "l"(b));
}

// ---------------- K1: dec_proj = hidden_dec @ Wa  [B, U] --------------------
__global__ void decproj_kernel(const float* __restrict__ hidden,
                               const float* __restrict__ Wa) {
    __shared__ float h[DDIM];
    const int b = blockIdx.x;
    const int tid = threadIdx.x;          // 512 threads, one per u
    h[tid] = hidden[b * DDIM + tid];
    __syncthreads();
    float acc0 = 0.f, acc1 = 0.f;
    #pragma unroll 8
    for (int k = 0; k < DDIM; k += 2) {
        acc0 = fmaf(h[k],     Wa[(size_t)k * UDIM + tid],          acc0);
        acc1 = fmaf(h[k + 1], Wa[(size_t)(k + 1) * UDIM + tid],    acc1);
    }
    g_dec_proj[b * UDIM + tid] = acc0 + acc1;
}

// ---------------- K2: fused  scores = Va . tanh(enc @ Ua + dec_proj) --------
// Grid: (S/BM, B), 256 threads. Each CTA: 64 rows of one batch, full U loop.
// Thread (ty=tid/16, tx=tid%16) owns a 4x4 micro-tile; inner product uses
// packed f32x2 FMAs (col-pairs packed).
__global__ __launch_bounds__(256) void scores_kernel(
    const float* __restrict__ enc, const float* __restrict__ Ua,
    const float* __restrict__ Va) {
    __shared__ float As[BM][BK + 4];     // 64 x 36 (pad kills conflicts)
    __shared__ float Bs[BK][BN];         // 32 x 64
    __shared__ float s_dp[UDIM];
    __shared__ float s_va[UDIM];

    const int tid = threadIdx.x;
    const int tx = tid & 15;
    const int ty = tid >> 4;
    const int b = blockIdx.y;
    const int stile = blockIdx.x;

    const float* Abase = enc + ((size_t)b * SLEN + (size_t)stile * BM) * EDIM;

    for (int i = tid; i < UDIM; i += 256) {
        s_dp[i] = g_dec_proj[b * UDIM + i];
        s_va[i] = Va[i];
    }

    float score_part[4] = {0.f, 0.f, 0.f, 0.f};

    for (int nt = 0; nt < NTILES; ++nt) {
        unsigned long long acc[4][2];
        #pragma unroll
        for (int i = 0; i < 4; ++i) { acc[i][0] = 0ull; acc[i][1] = 0ull; }

        for (int kt = 0; kt < KTILES; ++kt) {
            // ---- global loads (before sync so they overlap prior compute) --
            const int f0 = tid, f1 = tid + 256;
            const int ar0 = f0 >> 3, ac0 = (f0 & 7) << 2;
            const int ar1 = f1 >> 3, ac1 = (f1 & 7) << 2;
            float4 a0 = *reinterpret_cast<const float4*>(
                Abase + (size_t)ar0 * EDIM + kt * BK + ac0);
            float4 a1 = *reinterpret_cast<const float4*>(
                Abase + (size_t)ar1 * EDIM + kt * BK + ac1);
            const int br0 = f0 >> 4, bc0 = (f0 & 15) << 2;
            const int br1 = f1 >> 4, bc1 = (f1 & 15) << 2;
            float4 b0v = *reinterpret_cast<const float4*>(
                Ua + (size_t)(kt * BK + br0) * UDIM + nt * BN + bc0);
            float4 b1v = *reinterpret_cast<const float4*>(
                Ua + (size_t)(kt * BK + br1) * UDIM + nt * BN + bc1);

            __syncthreads();
            As[ar0][ac0 + 0] = a0.x; As[ar0][ac0 + 1] = a0.y;
            As[ar0][ac0 + 2] = a0.z; As[ar0][ac0 + 3] = a0.w;
            As[ar1][ac1 + 0] = a1.x; As[ar1][ac1 + 1] = a1.y;
            As[ar1][ac1 + 2] = a1.z; As[ar1][ac1 + 3] = a1.w;
            *reinterpret_cast<float4*>(&Bs[br0][bc0]) = b0v;
            *reinterpret_cast<float4*>(&Bs[br1][bc1]) = b1v;
            __syncthreads();

            #pragma unroll
            for (int kk = 0; kk < BK; ++kk) {
                const float av0 = As[ty * 4 + 0][kk];
                const float av1 = As[ty * 4 + 1][kk];
                const float av2 = As[ty * 4 + 2][kk];
                const float av3 = As[ty * 4 + 3][kk];
                const unsigned long long bp0 =
                    *reinterpret_cast<const unsigned long long*>(&Bs[kk][tx * 4]);
                const unsigned long long bp1 =
                    *reinterpret_cast<const unsigned long long*>(&Bs[kk][tx * 4 + 2]);
                const unsigned long long A0 = pack2(av0, av0);
                const unsigned long long A1 = pack2(av1, av1);
                const unsigned long long A2 = pack2(av2, av2);
                const unsigned long long A3 = pack2(av3, av3);
                fma2(acc[0][0], A0, bp0); fma2(acc[0][1], A0, bp1);
                fma2(acc[1][0], A1, bp0); fma2(acc[1][1], A1, bp1);
                fma2(acc[2][0], A2, bp0); fma2(acc[2][1], A2, bp1);
                fma2(acc[3][0], A3, bp0); fma2(acc[3][1], A3, bp1);
            }
        }

        // epilogue for this U-tile: tanh(c + dec_proj) * Va, reduce into rows
        #pragma unroll
        for (int i = 0; i < 4; ++i) {
            #pragma unroll
            for (int jp = 0; jp < 2; ++jp) {
                float lo, hi;
                unpack2(acc[i][jp], lo, hi);
                const int u0 = nt * BN + tx * 4 + jp * 2;
                score_part[i] += tanhf(lo + s_dp[u0])     * s_va[u0];
                score_part[i] += tanhf(hi + s_dp[u0 + 1]) * s_va[u0 + 1];
            }
        }
    }

    // reduce across the 16 tx threads sharing each row (width-16 butterflies)
    #pragma unroll
    for (int i = 0; i < 4; ++i) {
        float v = score_part[i];
        v += __shfl_xor_sync(0xffffffffu, v, 8, 16);
        v += __shfl_xor_sync(0xffffffffu, v, 4, 16);
        v += __shfl_xor_sync(0xffffffffu, v, 2, 16);
        v += __shfl_xor_sync(0xffffffffu, v, 1, 16);
        if (tx == 0)
            g_scores[b * SLEN + stile * BM + ty * 4 + i] = v;
    }
}

// ---------------- K3: softmax over S, in place -------------------------------
__device__ __forceinline__ float warp_max(float v) {
    #pragma unroll
    for (int o = 16; o; o >>= 1) v = fmaxf(v, __shfl_xor_sync(0xffffffffu, v, o));
    return v;
}
__device__ __forceinline__ float warp_sum(float v) {
    #pragma unroll
    for (int o = 16; o; o >>= 1) v += __shfl_xor_sync(0xffffffffu, v, o);
    return v;
}

__global__ void softmax_kernel() {
    const int b = blockIdx.x;
    const int tid = threadIdx.x;          // 256 threads, 4 scores each
    __shared__ float red[8];
    float4 v = *reinterpret_cast<float4*>(&g_scores[b * SLEN + tid * 4]);

    float m = fmaxf(fmaxf(v.x, v.y), fmaxf(v.z, v.w));
    m = warp_max(m);
    if ((tid & 31) == 0) red[tid >> 5] = m;
    __syncthreads();
    m = red[0];
    #pragma unroll
    for (int w = 1; w < 8; ++w) m = fmaxf(m, red[w]);

    float4 e;
    e.x = expf(v.x - m); e.y = expf(v.y - m);
    e.z = expf(v.z - m); e.w = expf(v.w - m);
    float s = e.x + e.y + e.z + e.w;
    s = warp_sum(s);
    __syncthreads();                       // red reuse
    if ((tid & 31) == 0) red[tid >> 5] = s;
    __syncthreads();
    s = 0.f;
    #pragma unroll
    for (int w = 0; w < 8; ++w) s += red[w];
    const float inv = 1.0f / s;
    e.x *= inv; e.y *= inv; e.z *= inv; e.w *= inv;
    *reinterpret_cast<float4*>(&g_scores[b * SLEN + tid * 4]) = e;
}

// ---------------- K4: context = alpha . enc  [B, E] --------------------------
// Grid (4, B), 512 threads: e = ec*128 + tid%128; 4 thread-groups split S.
__global__ __launch_bounds__(512) void context_kernel(
    const float* __restrict__ enc, float* __restrict__ out) {
    __shared__ float a[SLEN];
    __shared__ float partial[4][128];
    const int b = blockIdx.y;
    const int ec = blockIdx.x;
    const int tid = threadIdx.x;

    for (int i = tid; i < SLEN; i += 512) a[i] = g_scores[b * SLEN + i];
    __syncthreads();

    const int e = ec * 128 + (tid & 127);
    const int sg = tid >> 7;               // 0..3, each handles 256 s values
    const float* p = enc + (size_t)b * SLEN * EDIM + e;
    float acc0 = 0.f, acc1 = 0.f;
    const int s0 = sg * 256;
    #pragma unroll 4
    for (int s = s0; s < s0 + 256; s += 2) {
        acc0 = fmaf(a[s],     p[(size_t)s * EDIM],       acc0);
        acc1 = fmaf(a[s + 1], p[(size_t)(s + 1) * EDIM], acc1);
    }
    partial[sg][tid & 127] = acc0 + acc1;
    __syncthreads();
    if (tid < 128)
        out[b * EDIM + ec * 128 + tid] =
            partial[0][tid] + partial[1][tid] + partial[2][tid] + partial[3][tid];
}

// ---------------- launch -----------------------------------------------------
extern "C" void kernel_launch(void* const* d_in, const int* in_sizes, int n_in,
                              void* d_out, int out_size) {
    const float* enc = (const float*)d_in[0];   // [B, S, E]
    const float* hid = (const float*)d_in[1];   // [B, D]
    const float* Wa  = (const float*)d_in[2];   // [D, U]
    const float* Ua  = (const float*)d_in[3];   // [E, U]
    const float* Va  = (const float*)d_in[4];   // [U]
    float* out = (float*)d_out;                 // [B, E]

    decproj_kernel<<<BATCH, DDIM>>>(hid, Wa);
    dim3 g2(SLEN / BM, BATCH);
    scores_kernel<<<g2, 256>>>(enc, Ua, Va);
    softmax_kernel<<<BATCH, 256>>>();
    dim3 g4(4, BATCH);
    context_kernel<<<g4, 512>>>(enc, out);
}

// round 4
// speedup vs baseline: 2.4164x; 2.4164x over previous
#include <cuda_runtime.h>
#include <cuda_bf16.h>
#include <cstdint>

#define BATCH 32
#define SLEN  1024
#define EDIM  512
#define UDIM  512
#define DDIM  512

// ---------------- scratch ----------------------------------------------------
__device__ float g_dec_proj[BATCH * UDIM];
__device__ float g_spart[BATCH * SLEN * 4];      // per-utile score partials
__device__ float g_scores[BATCH * SLEN];         // alpha after softmax
__device__ __nv_bfloat16 g_UaT_hi[UDIM * EDIM];  // Ua^T split hi  [U][E]
__device__ __nv_bfloat16 g_UaT_lo[UDIM * EDIM];  // Ua^T split lo
__device__ float g_ctx_part[4][BATCH][EDIM];

// ---------------- helpers ----------------------------------------------------
__device__ __forceinline__ void cp_async16(uint32_t dst, const void* src) {
    asm volatile("cp.async.cg.shared.global [%0], [%1], 16;"
                 :: "r"(dst), "l"(src) : "memory");
}
__device__ __forceinline__ void cp_commit() {
    asm volatile("cp.async.commit_group;" ::: "memory");
}
template <int N>
__device__ __forceinline__ void cp_wait() {
    asm volatile("cp.async.wait_group %0;" :: "n"(N) : "memory");
}
__device__ __forceinline__ void mma_bf16(float& d0, float& d1, float& d2, float& d3,
                                         uint32_t a0, uint32_t a1, uint32_t a2,
                                         uint32_t a3, uint32_t b0, uint32_t b1) {
    asm volatile(
        "mma.sync.aligned.m16n8k16.row.col.f32.bf16.bf16.f32 "
        "{%0,%1,%2,%3}, {%4,%5,%6,%7}, {%8,%9}, {%0,%1,%2,%3};"
        : "+f"(d0), "+f"(d1), "+f"(d2), "+f"(d3)
        : "r"(a0), "r"(a1), "r"(a2), "r"(a3), "r"(b0), "r"(b1));
}
__device__ __forceinline__ float fast_tanh(float x) {
    const float e2x = __expf(2.0f * x);
    return 1.0f - __fdividef(2.0f, e2x + 1.0f);
}
__device__ __forceinline__ uint32_t pack_bf16(__nv_bfloat16 lo, __nv_bfloat16 hi) {
    return (uint32_t)__bfloat16_as_ushort(lo) |
           ((uint32_t)__bfloat16_as_ushort(hi) << 16);
}

// ---------------- K0: transpose+split Ua -> UaT_hi/lo -----------------------
__global__ void transpose_split_kernel(const float* __restrict__ Ua) {
    __shared__ float t[32][33];
    const int u0 = blockIdx.x * 32, e0 = blockIdx.y * 32;
    const int tx = threadIdx.x, ty = threadIdx.y;   // 32 x 8
    #pragma unroll
    for (int i = 0; i < 32; i += 8)
        t[ty + i][tx] = Ua[(size_t)(e0 + ty + i) * UDIM + u0 + tx];
    __syncthreads();
    #pragma unroll
    for (int i = 0; i < 32; i += 8) {
        const float v = t[tx][ty + i];
        const __nv_bfloat16 h = __float2bfloat16(v);
        const __nv_bfloat16 l = __float2bfloat16(v - __bfloat162float(h));
        g_UaT_hi[(size_t)(u0 + ty + i) * EDIM + e0 + tx] = h;
        g_UaT_lo[(size_t)(u0 + ty + i) * EDIM + e0 + tx] = l;
    }
}

// ---------------- K1: dec_proj = hidden_dec @ Wa ----------------------------
__global__ void decproj_kernel(const float* __restrict__ hidden,
                               const float* __restrict__ Wa) {
    __shared__ float h[DDIM];
    const int b = blockIdx.x;
    const int tid = threadIdx.x;
    h[tid] = hidden[b * DDIM + tid];
    __syncthreads();
    float a0 = 0.f, a1 = 0.f;
    #pragma unroll 8
    for (int k = 0; k < DDIM; k += 2) {
        a0 = fmaf(h[k],     Wa[(size_t)k * UDIM + tid],       a0);
        a1 = fmaf(h[k + 1], Wa[(size_t)(k + 1) * UDIM + tid], a1);
    }
    g_dec_proj[b * UDIM + tid] = a0 + a1;
}

// ---------------- K2: bf16x3 mma.sync fused scores --------------------------
// CTA: 128 s-rows x 128 u-cols, BK=32, 256 threads (8 warps: 4m x 2n).
// SMEM rows padded to 80B -> conflict-free fragment LDS.
#define RS   80
#define BK   32
#define KT   (EDIM / BK)          // 16
#define STG  (4 * 128 * RS)       // A_hi, A_lo, B_hi, B_lo per stage = 40960
#define OFF_AH 0
#define OFF_AL (128 * RS)
#define OFF_BH (2 * 128 * RS)
#define OFF_BL (3 * 128 * RS)
#define OFF_DP (2 * STG)          // 81920
#define OFF_VA (OFF_DP + 512)
#define OFF_SP (OFF_VA + 512)
#define SMEM_TOTAL (OFF_SP + 1024)

__global__ __launch_bounds__(256, 1) void scores_kernel(
    const float* __restrict__ enc, const float* __restrict__ Va) {
    extern __shared__ char smem[];
    const uint32_t sb = (uint32_t)__cvta_generic_to_shared(smem);

    const int tid = threadIdx.x;
    const int wid = tid >> 5, lane = tid & 31;
    const int g = lane >> 2, t = lane & 3;
    const int warp_m = (wid & 3) * 32;
    const int warp_n = (wid >> 2) * 64;
    const int stile = blockIdx.x, utile = blockIdx.y, b = blockIdx.z;

    float* s_dp = (float*)(smem + OFF_DP);
    float* s_va = (float*)(smem + OFF_VA);
    if (tid < 128) {
        s_dp[tid] = g_dec_proj[b * UDIM + utile * 128 + tid];
        s_va[tid] = Va[utile * 128 + tid];
    }

    const float* Ag = enc + ((size_t)b * SLEN + (size_t)stile * 128) * EDIM;
    const __nv_bfloat16* Bh = g_UaT_hi + (size_t)(utile * 128) * EDIM;
    const __nv_bfloat16* Bl = g_UaT_lo + (size_t)(utile * 128) * EDIM;

    // thread's A-load mapping: 4 chunks of 4 fp32
    int a_r[4], a_s[4];
    #pragma unroll
    for (int i = 0; i < 4; ++i) {
        const int c = tid + i * 256;
        a_r[i] = c >> 3;
        a_s[i] = c & 7;
    }
    // thread's B-load mapping: 2 row-segments per buffer
    int b_n[2], b_s[2];
    #pragma unroll
    for (int i = 0; i < 2; ++i) {
        const int c = tid + i * 256;
        b_n[i] = c >> 2;
        b_s[i] = c & 3;
    }

    float4 pf[4];
    // ---- prologue: A(0) to regs, B(0) via cp.async ----
    #pragma unroll
    for (int i = 0; i < 4; ++i)
        pf[i] = *reinterpret_cast<const float4*>(Ag + (size_t)a_r[i] * EDIM + a_s[i] * 4);
    #pragma unroll
    for (int i = 0; i < 2; ++i) {
        cp_async16(sb + OFF_BH + b_n[i] * RS + b_s[i] * 16,
                   Bh + (size_t)b_n[i] * EDIM + b_s[i] * 8);
        cp_async16(sb + OFF_BL + b_n[i] * RS + b_s[i] * 16,
                   Bl + (size_t)b_n[i] * EDIM + b_s[i] * 8);
    }
    cp_commit();

    float acc[2][8][4];
    #pragma unroll
    for (int mf = 0; mf < 2; ++mf)
        #pragma unroll
        for (int nf = 0; nf < 8; ++nf)
            #pragma unroll
            for (int r = 0; r < 4; ++r) acc[mf][nf][r] = 0.f;

    for (int kt = 0; kt < KT; ++kt) {
        const uint32_t so = (uint32_t)(kt & 1) * STG;
        // store A(kt) from regs with bf16 hi/lo split
        #pragma unroll
        for (int i = 0; i < 4; ++i) {
            const float x0 = pf[i].x, x1 = pf[i].y, x2 = pf[i].z, x3 = pf[i].w;
            const __nv_bfloat16 h0 = __float2bfloat16(x0);
            const __nv_bfloat16 h1 = __float2bfloat16(x1);
            const __nv_bfloat16 h2 = __float2bfloat16(x2);
            const __nv_bfloat16 h3 = __float2bfloat16(x3);
            const __nv_bfloat16 l0 = __float2bfloat16(x0 - __bfloat162float(h0));
            const __nv_bfloat16 l1 = __float2bfloat16(x1 - __bfloat162float(h1));
            const __nv_bfloat16 l2 = __float2bfloat16(x2 - __bfloat162float(h2));
            const __nv_bfloat16 l3 = __float2bfloat16(x3 - __bfloat162float(h3));
            const int off = a_r[i] * RS + a_s[i] * 8;
            *(uint32_t*)(smem + so + OFF_AH + off)     = pack_bf16(h0, h1);
            *(uint32_t*)(smem + so + OFF_AH + off + 4) = pack_bf16(h2, h3);
            *(uint32_t*)(smem + so + OFF_AL + off)     = pack_bf16(l0, l1);
            *(uint32_t*)(smem + so + OFF_AL + off + 4) = pack_bf16(l2, l3);
        }
        if (kt + 1 < KT) {
            const uint32_t sn = (uint32_t)((kt + 1) & 1) * STG;
            #pragma unroll
            for (int i = 0; i < 4; ++i)
                pf[i] = *reinterpret_cast<const float4*>(
                    Ag + (size_t)a_r[i] * EDIM + (kt + 1) * BK + a_s[i] * 4);
            #pragma unroll
            for (int i = 0; i < 2; ++i) {
                cp_async16(sn + sb + OFF_BH + b_n[i] * RS + b_s[i] * 16,
                           Bh + (size_t)b_n[i] * EDIM + (kt + 1) * BK + b_s[i] * 8);
                cp_async16(sn + sb + OFF_BL + b_n[i] * RS + b_s[i] * 16,
                           Bl + (size_t)b_n[i] * EDIM + (kt + 1) * BK + b_s[i] * 8);
            }
            cp_commit();
            cp_wait<1>();
        } else {
            cp_wait<0>();
        }
        __syncthreads();

        // ---- compute on stage so ----
        const char* Ahp = smem + so + OFF_AH;
        const char* Alp = smem + so + OFF_AL;
        const char* Bhp = smem + so + OFF_BH;
        const char* Blp = smem + so + OFF_BL;
        #pragma unroll
        for (int k16 = 0; k16 < 2; ++k16) {
            const int kb = k16 * 32 + t * 4;   // byte offset of this lane's k-pair
            uint32_t ah[2][4], al[2][4], bb[8][2];
            #pragma unroll
            for (int mf = 0; mf < 2; ++mf) {
                const int rb = warp_m + mf * 16 + g;
                ah[mf][0] = *(const uint32_t*)(Ahp + rb * RS + kb);
                ah[mf][1] = *(const uint32_t*)(Ahp + (rb + 8) * RS + kb);
                ah[mf][2] = *(const uint32_t*)(Ahp + rb * RS + kb + 16);
                ah[mf][3] = *(const uint32_t*)(Ahp + (rb + 8) * RS + kb + 16);
                al[mf][0] = *(const uint32_t*)(Alp + rb * RS + kb);
                al[mf][1] = *(const uint32_t*)(Alp + (rb + 8) * RS + kb);
                al[mf][2] = *(const uint32_t*)(Alp + rb * RS + kb + 16);
                al[mf][3] = *(const uint32_t*)(Alp + (rb + 8) * RS + kb + 16);
            }
            #pragma unroll
            for (int nf = 0; nf < 8; ++nf) {
                const int nr = warp_n + nf * 8 + g;
                bb[nf][0] = *(const uint32_t*)(Bhp + nr * RS + kb);
                bb[nf][1] = *(const uint32_t*)(Bhp + nr * RS + kb + 16);
            }
            // pass 1: A_hi * B_hi
            #pragma unroll
            for (int nf = 0; nf < 8; ++nf)
                #pragma unroll
                for (int mf = 0; mf < 2; ++mf)
                    mma_bf16(acc[mf][nf][0], acc[mf][nf][1], acc[mf][nf][2],
                             acc[mf][nf][3], ah[mf][0], ah[mf][1], ah[mf][2],
                             ah[mf][3], bb[nf][0], bb[nf][1]);
            // pass 2: A_lo * B_hi (b_hi still live)
            #pragma unroll
            for (int nf = 0; nf < 8; ++nf)
                #pragma unroll
                for (int mf = 0; mf < 2; ++mf)
                    mma_bf16(acc[mf][nf][0], acc[mf][nf][1], acc[mf][nf][2],
                             acc[mf][nf][3], al[mf][0], al[mf][1], al[mf][2],
                             al[mf][3], bb[nf][0], bb[nf][1]);
            // pass 3: A_hi * B_lo (overwrite b regs)
            #pragma unroll
            for (int nf = 0; nf < 8; ++nf) {
                const int nr = warp_n + nf * 8 + g;
                bb[nf][0] = *(const uint32_t*)(Blp + nr * RS + kb);
                bb[nf][1] = *(const uint32_t*)(Blp + nr * RS + kb + 16);
            }
            #pragma unroll
            for (int nf = 0; nf < 8; ++nf)
                #pragma unroll
                for (int mf = 0; mf < 2; ++mf)
                    mma_bf16(acc[mf][nf][0], acc[mf][nf][1], acc[mf][nf][2],
                             acc[mf][nf][3], ah[mf][0], ah[mf][1], ah[mf][2],
                             ah[mf][3], bb[nf][0], bb[nf][1]);
        }
        __syncthreads();
    }

    // ---- epilogue: tanh(x + dp) * Va, reduce to row sums ----
    float rs[4] = {0.f, 0.f, 0.f, 0.f};
    #pragma unroll
    for (int mf = 0; mf < 2; ++mf)
        #pragma unroll
        for (int nf = 0; nf < 8; ++nf) {
            const int un = warp_n + nf * 8 + 2 * t;
            const float dp0 = s_dp[un], dp1 = s_dp[un + 1];
            const float v0 = s_va[un], v1 = s_va[un + 1];
            rs[mf * 2 + 0] += fast_tanh(acc[mf][nf][0] + dp0) * v0 +
                              fast_tanh(acc[mf][nf][1] + dp1) * v1;
            rs[mf * 2 + 1] += fast_tanh(acc[mf][nf][2] + dp0) * v0 +
                              fast_tanh(acc[mf][nf][3] + dp1) * v1;
        }
    #pragma unroll
    for (int j = 0; j < 4; ++j) {
        rs[j] += __shfl_xor_sync(0xffffffffu, rs[j], 1);
        rs[j] += __shfl_xor_sync(0xffffffffu, rs[j], 2);
    }
    float* s_sp = (float*)(smem + OFF_SP);   // [128][2]
    const int nw = wid >> 2;
    if (t == 0) {
        s_sp[(warp_m + g) * 2 + nw]      = rs[0];
        s_sp[(warp_m + 8 + g) * 2 + nw]  = rs[1];
        s_sp[(warp_m + 16 + g) * 2 + nw] = rs[2];
        s_sp[(warp_m + 24 + g) * 2 + nw] = rs[3];
    }
    __syncthreads();
    if (tid < 128) {
        const float s = s_sp[tid * 2] + s_sp[tid * 2 + 1];
        g_spart[((size_t)b * SLEN + stile * 128 + tid) * 4 + utile] = s;
    }
}

// ---------------- K3: sum partials + softmax --------------------------------
__device__ __forceinline__ float warp_max(float v) {
    #pragma unroll
    for (int o = 16; o; o >>= 1) v = fmaxf(v, __shfl_xor_sync(0xffffffffu, v, o));
    return v;
}
__device__ __forceinline__ float warp_sum(float v) {
    #pragma unroll
    for (int o = 16; o; o >>= 1) v += __shfl_xor_sync(0xffffffffu, v, o);
    return v;
}
__global__ void softmax_kernel() {
    const int b = blockIdx.x;
    const int tid = threadIdx.x;          // 256 threads, 4 scores each
    __shared__ float red[8];
    float sc[4];
    #pragma unroll
    for (int j = 0; j < 4; ++j) {
        const float4 p = *reinterpret_cast<const float4*>(
            &g_spart[((size_t)b * SLEN + tid * 4 + j) * 4]);
        sc[j] = (p.x + p.y) + (p.z + p.w);
    }
    float m = fmaxf(fmaxf(sc[0], sc[1]), fmaxf(sc[2], sc[3]));
    m = warp_max(m);
    if ((tid & 31) == 0) red[tid >> 5] = m;
    __syncthreads();
    m = red[0];
    #pragma unroll
    for (int w = 1; w < 8; ++w) m = fmaxf(m, red[w]);

    float e[4], s = 0.f;
    #pragma unroll
    for (int j = 0; j < 4; ++j) { e[j] = expf(sc[j] - m); s += e[j]; }
    s = warp_sum(s);
    __syncthreads();
    if ((tid & 31) == 0) red[tid >> 5] = s;
    __syncthreads();
    s = 0.f;
    #pragma unroll
    for (int w = 0; w < 8; ++w) s += red[w];
    const float inv = 1.0f / s;
    float4 o;
    o.x = e[0] * inv; o.y = e[1] * inv; o.z = e[2] * inv; o.w = e[3] * inv;
    *reinterpret_cast<float4*>(&g_scores[b * SLEN + tid * 4]) = o;
}

// ---------------- K4: context partials  grid(B, 4) x 512 --------------------
__global__ __launch_bounds__(512) void context_kernel(const float* __restrict__ enc) {
    __shared__ float a[256];
    __shared__ float part[4][512];
    const int b = blockIdx.x, sg = blockIdx.y;
    const int tid = threadIdx.x;
    const int s_base = sg * 256;

    if (tid < 256) a[tid] = g_scores[b * SLEN + s_base + tid];
    __syncthreads();

    const int e4 = (tid & 127) * 4;
    const int sr = tid >> 7;                  // 0..3
    const float* p = enc + ((size_t)b * SLEN + s_base) * EDIM + e4;
    float4 acc = {0.f, 0.f, 0.f, 0.f};
    for (int s0 = sr; s0 < 256; s0 += 16) {
        float4 v0 = *reinterpret_cast<const float4*>(p + (size_t)(s0)      * EDIM);
        float4 v1 = *reinterpret_cast<const float4*>(p + (size_t)(s0 + 4)  * EDIM);
        float4 v2 = *reinterpret_cast<const float4*>(p + (size_t)(s0 + 8)  * EDIM);
        float4 v3 = *reinterpret_cast<const float4*>(p + (size_t)(s0 + 12) * EDIM);
        const float a0 = a[s0], a1 = a[s0 + 4], a2 = a[s0 + 8], a3 = a[s0 + 12];
        acc.x = fmaf(a0, v0.x, fmaf(a1, v1.x, fmaf(a2, v2.x, fmaf(a3, v3.x, acc.x))));
        acc.y = fmaf(a0, v0.y, fmaf(a1, v1.y, fmaf(a2, v2.y, fmaf(a3, v3.y, acc.y))));
        acc.z = fmaf(a0, v0.z, fmaf(a1, v1.z, fmaf(a2, v2.z, fmaf(a3, v3.z, acc.z))));
        acc.w = fmaf(a0, v0.w, fmaf(a1, v1.w, fmaf(a2, v2.w, fmaf(a3, v3.w, acc.w))));
    }
    *reinterpret_cast<float4*>(&part[sr][e4]) = acc;
    __syncthreads();
    if (tid < 128) {
        float4 r0 = *reinterpret_cast<float4*>(&part[0][tid * 4]);
        float4 r1 = *reinterpret_cast<float4*>(&part[1][tid * 4]);
        float4 r2 = *reinterpret_cast<float4*>(&part[2][tid * 4]);
        float4 r3 = *reinterpret_cast<float4*>(&part[3][tid * 4]);
        float4 o;
        o.x = r0.x + r1.x + r2.x + r3.x;
        o.y = r0.y + r1.y + r2.y + r3.y;
        o.z = r0.z + r1.z + r2.z + r3.z;
        o.w = r0.w + r1.w + r2.w + r3.w;
        *reinterpret_cast<float4*>(&g_ctx_part[sg][b][tid * 4]) = o;
    }
}

// ---------------- K5: reduce 4 context partials -----------------------------
__global__ void ctx_reduce_kernel(float* __restrict__ out) {
    const int b = blockIdx.x;
    const int tid = threadIdx.x;              // 128 threads, float4
    float4 r0 = *reinterpret_cast<float4*>(&g_ctx_part[0][b][tid * 4]);
    float4 r1 = *reinterpret_cast<float4*>(&g_ctx_part[1][b][tid * 4]);
    float4 r2 = *reinterpret_cast<float4*>(&g_ctx_part[2][b][tid * 4]);
    float4 r3 = *reinterpret_cast<float4*>(&g_ctx_part[3][b][tid * 4]);
    float4 o;
    o.x = r0.x + r1.x + r2.x + r3.x;
    o.y = r0.y + r1.y + r2.y + r3.y;
    o.z = r0.z + r1.z + r2.z + r3.z;
    o.w = r0.w + r1.w + r2.w + r3.w;
    *reinterpret_cast<float4*>(&out[b * EDIM + tid * 4]) = o;
}

// ---------------- launch -----------------------------------------------------
extern "C" void kernel_launch(void* const* d_in, const int* in_sizes, int n_in,
                              void* d_out, int out_size) {
    const float* enc = (const float*)d_in[0];   // [B, S, E]
    const float* hid = (const float*)d_in[1];   // [B, D]
    const float* Wa  = (const float*)d_in[2];   // [D, U]
    const float* Ua  = (const float*)d_in[3];   // [E, U]
    const float* Va  = (const float*)d_in[4];   // [U]
    float* out = (float*)d_out;                 // [B, E]

    cudaFuncSetAttribute(scores_kernel,
                         cudaFuncAttributeMaxDynamicSharedMemorySize, SMEM_TOTAL);

    dim3 gt(16, 16);
    transpose_split_kernel<<<gt, dim3(32, 8)>>>(Ua);
    decproj_kernel<<<BATCH, DDIM>>>(hid, Wa);
    dim3 g2(SLEN / 128, UDIM / 128, BATCH);
    scores_kernel<<<g2, 256, SMEM_TOTAL>>>(enc, Va);
    softmax_kernel<<<BATCH, 256>>>();
    dim3 g4(BATCH, 4);
    context_kernel<<<g4, 512>>>(enc);
    ctx_reduce_kernel<<<BATCH, 128>>>(out);
}

// round 5
// speedup vs baseline: 2.5223x; 1.0438x over previous
#include <cuda_runtime.h>
#include <cuda_bf16.h>
#include <cstdint>

#define BATCH 32
#define SLEN  1024
#define EDIM  512
#define UDIM  512
#define DDIM  512

// ---------------- scratch ----------------------------------------------------
__device__ float g_dec_proj[BATCH * UDIM];
__device__ float g_spart[BATCH * SLEN * 2];      // per-utile score partials (2)
__device__ float g_scores[BATCH * SLEN];         // alpha after softmax
__device__ __nv_bfloat16 g_UaT_hi[UDIM * EDIM];  // Ua^T split hi  [U][E]
__device__ __nv_bfloat16 g_UaT_lo[UDIM * EDIM];  // Ua^T split lo
__device__ float g_ctx_part[4][BATCH][EDIM];

// ---------------- helpers ----------------------------------------------------
__device__ __forceinline__ void cp_async16(uint32_t dst, const void* src) {
    asm volatile("cp.async.cg.shared.global [%0], [%1], 16;"
                 :: "r"(dst), "l"(src) : "memory");
}
__device__ __forceinline__ void cp_commit() {
    asm volatile("cp.async.commit_group;" ::: "memory");
}
template <int N>
__device__ __forceinline__ void cp_wait() {
    asm volatile("cp.async.wait_group %0;" :: "n"(N) : "memory");
}
__device__ __forceinline__ void mma_bf16(float& d0, float& d1, float& d2, float& d3,
                                         uint32_t a0, uint32_t a1, uint32_t a2,
                                         uint32_t a3, uint32_t b0, uint32_t b1) {
    asm volatile(
        "mma.sync.aligned.m16n8k16.row.col.f32.bf16.bf16.f32 "
        "{%0,%1,%2,%3}, {%4,%5,%6,%7}, {%8,%9}, {%0,%1,%2,%3};"
        : "+f"(d0), "+f"(d1), "+f"(d2), "+f"(d3)
        : "r"(a0), "r"(a1), "r"(a2), "r"(a3), "r"(b0), "r"(b1));
}
__device__ __forceinline__ float fast_tanh(float x) {
    const float e2x = __expf(2.0f * x);
    return 1.0f - __fdividef(2.0f, e2x + 1.0f);
}
__device__ __forceinline__ uint32_t pack_bf16(__nv_bfloat16 lo, __nv_bfloat16 hi) {
    return (uint32_t)__bfloat16_as_ushort(lo) |
           ((uint32_t)__bfloat16_as_ushort(hi) << 16);
}

// ---------------- K0: transpose+split Ua -> UaT_hi/lo -----------------------
__global__ void transpose_split_kernel(const float* __restrict__ Ua) {
    __shared__ float t[32][33];
    const int u0 = blockIdx.x * 32, e0 = blockIdx.y * 32;
    const int tx = threadIdx.x, ty = threadIdx.y;   // 32 x 8
    #pragma unroll
    for (int i = 0; i < 32; i += 8)
        t[ty + i][tx] = Ua[(size_t)(e0 + ty + i) * UDIM + u0 + tx];
    __syncthreads();
    #pragma unroll
    for (int i = 0; i < 32; i += 8) {
        const float v = t[tx][ty + i];
        const __nv_bfloat16 h = __float2bfloat16(v);
        const __nv_bfloat16 l = __float2bfloat16(v - __bfloat162float(h));
        g_UaT_hi[(size_t)(u0 + ty + i) * EDIM + e0 + tx] = h;
        g_UaT_lo[(size_t)(u0 + ty + i) * EDIM + e0 + tx] = l;
    }
}

// ---------------- K1: dec_proj = hidden_dec @ Wa ----------------------------
__global__ void decproj_kernel(const float* __restrict__ hidden,
                               const float* __restrict__ Wa) {
    __shared__ float h[DDIM];
    const int b = blockIdx.x;
    const int tid = threadIdx.x;
    h[tid] = hidden[b * DDIM + tid];
    __syncthreads();
    float a0 = 0.f, a1 = 0.f;
    #pragma unroll 8
    for (int k = 0; k < DDIM; k += 2) {
        a0 = fmaf(h[k],     Wa[(size_t)k * UDIM + tid],       a0);
        a1 = fmaf(h[k + 1], Wa[(size_t)(k + 1) * UDIM + tid], a1);
    }
    g_dec_proj[b * UDIM + tid] = a0 + a1;
}

// ---------------- K2: bf16x3 mma.sync fused scores --------------------------
// CTA: 128 s-rows x 256 u-cols, BK=32, 256 threads (8 warps: 2m x 4n),
// warp tile 64x64. SMEM rows padded to 80B.
#define RS   80
#define BK   32
#define KT   (EDIM / BK)          // 16
#define OFF_AH 0                  // 128*80 = 10240
#define OFF_AL 10240
#define OFF_BH 20480              // 256*80 = 20480
#define OFF_BL 40960
#define STG    61440              // bytes per stage
#define OFF_DP (2 * STG)          // 122880, 256 floats
#define OFF_VA (OFF_DP + 1024)
#define OFF_SP (OFF_VA + 1024)    // 128 rows x 4 warp-cols
#define SMEM_TOTAL (OFF_SP + 2048)

__global__ __launch_bounds__(256, 1) void scores_kernel(
    const float* __restrict__ enc, const float* __restrict__ Va) {
    extern __shared__ char smem[];
    const uint32_t sb = (uint32_t)__cvta_generic_to_shared(smem);

    const int tid = threadIdx.x;
    const int wid = tid >> 5, lane = tid & 31;
    const int g = lane >> 2, t = lane & 3;
    const int warp_m = (wid & 1) * 64;
    const int warp_n = (wid >> 1) * 64;
    const int stile = blockIdx.x, utile = blockIdx.y, b = blockIdx.z;

    float* s_dp = (float*)(smem + OFF_DP);
    float* s_va = (float*)(smem + OFF_VA);
    if (tid < 256) {
        s_dp[tid] = g_dec_proj[b * UDIM + utile * 256 + tid];
        s_va[tid] = Va[utile * 256 + tid];
    }

    const float* Ag = enc + ((size_t)b * SLEN + (size_t)stile * 128) * EDIM;
    const __nv_bfloat16* Bh = g_UaT_hi + (size_t)(utile * 256) * EDIM;
    const __nv_bfloat16* Bl = g_UaT_lo + (size_t)(utile * 256) * EDIM;

    // A-load mapping: 4 chunks of float4 (128 rows x 8 float4-chunks)
    int a_r[4], a_s[4];
    #pragma unroll
    for (int i = 0; i < 4; ++i) {
        const int c = tid + i * 256;
        a_r[i] = c >> 3;
        a_s[i] = c & 7;
    }
    // B-load mapping: 4 chunks of 16B per buffer (256 rows x 4 segs)
    int b_n[4], b_s[4];
    #pragma unroll
    for (int i = 0; i < 4; ++i) {
        const int c = tid + i * 256;
        b_n[i] = c >> 2;
        b_s[i] = c & 3;
    }

    float4 pf[4];
    // ---- prologue: A(0) to regs, B(0) via cp.async ----
    #pragma unroll
    for (int i = 0; i < 4; ++i)
        pf[i] = *reinterpret_cast<const float4*>(Ag + (size_t)a_r[i] * EDIM + a_s[i] * 4);
    #pragma unroll
    for (int i = 0; i < 4; ++i) {
        cp_async16(sb + OFF_BH + b_n[i] * RS + b_s[i] * 16,
                   Bh + (size_t)b_n[i] * EDIM + b_s[i] * 8);
        cp_async16(sb + OFF_BL + b_n[i] * RS + b_s[i] * 16,
                   Bl + (size_t)b_n[i] * EDIM + b_s[i] * 8);
    }
    cp_commit();

    float acc[4][8][4];
    #pragma unroll
    for (int mf = 0; mf < 4; ++mf)
        #pragma unroll
        for (int nf = 0; nf < 8; ++nf)
            #pragma unroll
            for (int r = 0; r < 4; ++r) acc[mf][nf][r] = 0.f;

    for (int kt = 0; kt < KT; ++kt) {
        const uint32_t so = (uint32_t)(kt & 1) * STG;
        // store A(kt) from regs with bf16 hi/lo split
        #pragma unroll
        for (int i = 0; i < 4; ++i) {
            const float x0 = pf[i].x, x1 = pf[i].y, x2 = pf[i].z, x3 = pf[i].w;
            const __nv_bfloat16 h0 = __float2bfloat16(x0);
            const __nv_bfloat16 h1 = __float2bfloat16(x1);
            const __nv_bfloat16 h2 = __float2bfloat16(x2);
            const __nv_bfloat16 h3 = __float2bfloat16(x3);
            const __nv_bfloat16 l0 = __float2bfloat16(x0 - __bfloat162float(h0));
            const __nv_bfloat16 l1 = __float2bfloat16(x1 - __bfloat162float(h1));
            const __nv_bfloat16 l2 = __float2bfloat16(x2 - __bfloat162float(h2));
            const __nv_bfloat16 l3 = __float2bfloat16(x3 - __bfloat162float(h3));
            const int off = a_r[i] * RS + a_s[i] * 8;
            *(uint32_t*)(smem + so + OFF_AH + off)     = pack_bf16(h0, h1);
            *(uint32_t*)(smem + so + OFF_AH + off + 4) = pack_bf16(h2, h3);
            *(uint32_t*)(smem + so + OFF_AL + off)     = pack_bf16(l0, l1);
            *(uint32_t*)(smem + so + OFF_AL + off + 4) = pack_bf16(l2, l3);
        }
        if (kt + 1 < KT) {
            const uint32_t sn = (uint32_t)((kt + 1) & 1) * STG;
            #pragma unroll
            for (int i = 0; i < 4; ++i)
                pf[i] = *reinterpret_cast<const float4*>(
                    Ag + (size_t)a_r[i] * EDIM + (kt + 1) * BK + a_s[i] * 4);
            #pragma unroll
            for (int i = 0; i < 4; ++i) {
                cp_async16(sn + sb + OFF_BH + b_n[i] * RS + b_s[i] * 16,
                           Bh + (size_t)b_n[i] * EDIM + (kt + 1) * BK + b_s[i] * 8);
                cp_async16(sn + sb + OFF_BL + b_n[i] * RS + b_s[i] * 16,
                           Bl + (size_t)b_n[i] * EDIM + (kt + 1) * BK + b_s[i] * 8);
            }
            cp_commit();
            cp_wait<1>();
        } else {
            cp_wait<0>();
        }
        __syncthreads();

        // ---- compute on stage so ----
        const char* Ahp = smem + so + OFF_AH;
        const char* Alp = smem + so + OFF_AL;
        const char* Bhp = smem + so + OFF_BH;
        const char* Blp = smem + so + OFF_BL;
        #pragma unroll
        for (int k16 = 0; k16 < 2; ++k16) {
            const int kb = k16 * 32 + t * 4;
            uint32_t ah[4][4], bb[8][2];
            #pragma unroll
            for (int mf = 0; mf < 4; ++mf) {
                const int rb = warp_m + mf * 16 + g;
                ah[mf][0] = *(const uint32_t*)(Ahp + rb * RS + kb);
                ah[mf][1] = *(const uint32_t*)(Ahp + (rb + 8) * RS + kb);
                ah[mf][2] = *(const uint32_t*)(Ahp + rb * RS + kb + 16);
                ah[mf][3] = *(const uint32_t*)(Ahp + (rb + 8) * RS + kb + 16);
            }
            #pragma unroll
            for (int nf = 0; nf < 8; ++nf) {
                const int nr = warp_n + nf * 8 + g;
                bb[nf][0] = *(const uint32_t*)(Bhp + nr * RS + kb);
                bb[nf][1] = *(const uint32_t*)(Bhp + nr * RS + kb + 16);
            }
            // pass 1: A_hi * B_hi
            #pragma unroll
            for (int nf = 0; nf < 8; ++nf)
                #pragma unroll
                for (int mf = 0; mf < 4; ++mf)
                    mma_bf16(acc[mf][nf][0], acc[mf][nf][1], acc[mf][nf][2],
                             acc[mf][nf][3], ah[mf][0], ah[mf][1], ah[mf][2],
                             ah[mf][3], bb[nf][0], bb[nf][1]);
            // pass 2: A_lo * B_hi  (al loaded per-mf to cap live regs)
            #pragma unroll
            for (int mf = 0; mf < 4; ++mf) {
                const int rb = warp_m + mf * 16 + g;
                uint32_t al0 = *(const uint32_t*)(Alp + rb * RS + kb);
                uint32_t al1 = *(const uint32_t*)(Alp + (rb + 8) * RS + kb);
                uint32_t al2 = *(const uint32_t*)(Alp + rb * RS + kb + 16);
                uint32_t al3 = *(const uint32_t*)(Alp + (rb + 8) * RS + kb + 16);
                #pragma unroll
                for (int nf = 0; nf < 8; ++nf)
                    mma_bf16(acc[mf][nf][0], acc[mf][nf][1], acc[mf][nf][2],
                             acc[mf][nf][3], al0, al1, al2, al3,
                             bb[nf][0], bb[nf][1]);
            }
            // pass 3: A_hi * B_lo (overwrite b regs)
            #pragma unroll
            for (int nf = 0; nf < 8; ++nf) {
                const int nr = warp_n + nf * 8 + g;
                bb[nf][0] = *(const uint32_t*)(Blp + nr * RS + kb);
                bb[nf][1] = *(const uint32_t*)(Blp + nr * RS + kb + 16);
            }
            #pragma unroll
            for (int nf = 0; nf < 8; ++nf)
                #pragma unroll
                for (int mf = 0; mf < 4; ++mf)
                    mma_bf16(acc[mf][nf][0], acc[mf][nf][1], acc[mf][nf][2],
                             acc[mf][nf][3], ah[mf][0], ah[mf][1], ah[mf][2],
                             ah[mf][3], bb[nf][0], bb[nf][1]);
        }
        __syncthreads();
    }

    // ---- epilogue: tanh(x + dp) * Va, reduce to row sums ----
    float rs[8];
    #pragma unroll
    for (int j = 0; j < 8; ++j) rs[j] = 0.f;
    #pragma unroll
    for (int mf = 0; mf < 4; ++mf)
        #pragma unroll
        for (int nf = 0; nf < 8; ++nf) {
            const int un = warp_n + nf * 8 + 2 * t;
            const float dp0 = s_dp[un], dp1 = s_dp[un + 1];
            const float v0 = s_va[un], v1 = s_va[un + 1];
            rs[mf * 2 + 0] += fast_tanh(acc[mf][nf][0] + dp0) * v0 +
                              fast_tanh(acc[mf][nf][1] + dp1) * v1;
            rs[mf * 2 + 1] += fast_tanh(acc[mf][nf][2] + dp0) * v0 +
                              fast_tanh(acc[mf][nf][3] + dp1) * v1;
        }
    #pragma unroll
    for (int j = 0; j < 8; ++j) {
        rs[j] += __shfl_xor_sync(0xffffffffu, rs[j], 1);
        rs[j] += __shfl_xor_sync(0xffffffffu, rs[j], 2);
    }
    float* s_sp = (float*)(smem + OFF_SP);   // [128 rows][4 n-warps]
    const int nw = wid >> 1;
    if (t == 0) {
        #pragma unroll
        for (int mf = 0; mf < 4; ++mf) {
            s_sp[(warp_m + mf * 16 + g) * 4 + nw]     = rs[mf * 2];
            s_sp[(warp_m + mf * 16 + 8 + g) * 4 + nw] = rs[mf * 2 + 1];
        }
    }
    __syncthreads();
    if (tid < 128) {
        const float s = s_sp[tid * 4] + s_sp[tid * 4 + 1] +
                        s_sp[tid * 4 + 2] + s_sp[tid * 4 + 3];
        g_spart[((size_t)b * SLEN + stile * 128 + tid) * 2 + utile] = s;
    }
}

// ---------------- K3: sum partials + softmax --------------------------------
__device__ __forceinline__ float warp_max(float v) {
    #pragma unroll
    for (int o = 16; o; o >>= 1) v = fmaxf(v, __shfl_xor_sync(0xffffffffu, v, o));
    return v;
}
__device__ __forceinline__ float warp_sum(float v) {
    #pragma unroll
    for (int o = 16; o; o >>= 1) v += __shfl_xor_sync(0xffffffffu, v, o);
    return v;
}
__global__ void softmax_kernel() {
    const int b = blockIdx.x;
    const int tid = threadIdx.x;          // 256 threads, 4 scores each
    __shared__ float red[8];
    float sc[4];
    #pragma unroll
    for (int j = 0; j < 4; ++j) {
        const float2 p = *reinterpret_cast<const float2*>(
            &g_spart[((size_t)b * SLEN + tid * 4 + j) * 2]);
        sc[j] = p.x + p.y;
    }
    float m = fmaxf(fmaxf(sc[0], sc[1]), fmaxf(sc[2], sc[3]));
    m = warp_max(m);
    if ((tid & 31) == 0) red[tid >> 5] = m;
    __syncthreads();
    m = red[0];
    #pragma unroll
    for (int w = 1; w < 8; ++w) m = fmaxf(m, red[w]);

    float e[4], s = 0.f;
    #pragma unroll
    for (int j = 0; j < 4; ++j) { e[j] = expf(sc[j] - m); s += e[j]; }
    s = warp_sum(s);
    __syncthreads();
    if ((tid & 31) == 0) red[tid >> 5] = s;
    __syncthreads();
    s = 0.f;
    #pragma unroll
    for (int w = 0; w < 8; ++w) s += red[w];
    const float inv = 1.0f / s;
    float4 o;
    o.x = e[0] * inv; o.y = e[1] * inv; o.z = e[2] * inv; o.w = e[3] * inv;
    *reinterpret_cast<float4*>(&g_scores[b * SLEN + tid * 4]) = o;
}

// ---------------- K4: context partials  grid(B, 4) x 512 --------------------
__global__ __launch_bounds__(512) void context_kernel(const float* __restrict__ enc) {
    __shared__ float a[256];
    __shared__ float part[4][512];
    const int b = blockIdx.x, sg = blockIdx.y;
    const int tid = threadIdx.x;
    const int s_base = sg * 256;

    if (tid < 256) a[tid] = g_scores[b * SLEN + s_base + tid];
    __syncthreads();

    const int e4 = (tid & 127) * 4;
    const int sr = tid >> 7;                  // 0..3
    const float* p = enc + ((size_t)b * SLEN + s_base) * EDIM + e4;
    float4 acc = {0.f, 0.f, 0.f, 0.f};
    for (int s0 = sr; s0 < 256; s0 += 16) {
        float4 v0 = *reinterpret_cast<const float4*>(p + (size_t)(s0)      * EDIM);
        float4 v1 = *reinterpret_cast<const float4*>(p + (size_t)(s0 + 4)  * EDIM);
        float4 v2 = *reinterpret_cast<const float4*>(p + (size_t)(s0 + 8)  * EDIM);
        float4 v3 = *reinterpret_cast<const float4*>(p + (size_t)(s0 + 12) * EDIM);
        const float a0 = a[s0], a1 = a[s0 + 4], a2 = a[s0 + 8], a3 = a[s0 + 12];
        acc.x = fmaf(a0, v0.x, fmaf(a1, v1.x, fmaf(a2, v2.x, fmaf(a3, v3.x, acc.x))));
        acc.y = fmaf(a0, v0.y, fmaf(a1, v1.y, fmaf(a2, v2.y, fmaf(a3, v3.y, acc.y))));
        acc.z = fmaf(a0, v0.z, fmaf(a1, v1.z, fmaf(a2, v2.z, fmaf(a3, v3.z, acc.z))));
        acc.w = fmaf(a0, v0.w, fmaf(a1, v1.w, fmaf(a2, v2.w, fmaf(a3, v3.w, acc.w))));
    }
    *reinterpret_cast<float4*>(&part[sr][e4]) = acc;
    __syncthreads();
    if (tid < 128) {
        float4 r0 = *reinterpret_cast<float4*>(&part[0][tid * 4]);
        float4 r1 = *reinterpret_cast<float4*>(&part[1][tid * 4]);
        float4 r2 = *reinterpret_cast<float4*>(&part[2][tid * 4]);
        float4 r3 = *reinterpret_cast<float4*>(&part[3][tid * 4]);
        float4 o;
        o.x = r0.x + r1.x + r2.x + r3.x;
        o.y = r0.y + r1.y + r2.y + r3.y;
        o.z = r0.z + r1.z + r2.z + r3.z;
        o.w = r0.w + r1.w + r2.w + r3.w;
        *reinterpret_cast<float4*>(&g_ctx_part[sg][b][tid * 4]) = o;
    }
}

// ---------------- K5: reduce 4 context partials -----------------------------
__global__ void ctx_reduce_kernel(float* __restrict__ out) {
    const int b = blockIdx.x;
    const int tid = threadIdx.x;              // 128 threads, float4
    float4 r0 = *reinterpret_cast<float4*>(&g_ctx_part[0][b][tid * 4]);
    float4 r1 = *reinterpret_cast<float4*>(&g_ctx_part[1][b][tid * 4]);
    float4 r2 = *reinterpret_cast<float4*>(&g_ctx_part[2][b][tid * 4]);
    float4 r3 = *reinterpret_cast<float4*>(&g_ctx_part[3][b][tid * 4]);
    float4 o;
    o.x = r0.x + r1.x + r2.x + r3.x;
    o.y = r0.y + r1.y + r2.y + r3.y;
    o.z = r0.z + r1.z + r2.z + r3.z;
    o.w = r0.w + r1.w + r2.w + r3.w;
    *reinterpret_cast<float4*>(&out[b * EDIM + tid * 4]) = o;
}

// ---------------- launch -----------------------------------------------------
extern "C" void kernel_launch(void* const* d_in, const int* in_sizes, int n_in,
                              void* d_out, int out_size) {
    const float* enc = (const float*)d_in[0];   // [B, S, E]
    const float* hid = (const float*)d_in[1];   // [B, D]
    const float* Wa  = (const float*)d_in[2];   // [D, U]
    const float* Ua  = (const float*)d_in[3];   // [E, U]
    const float* Va  = (const float*)d_in[4];   // [U]
    float* out = (float*)d_out;                 // [B, E]

    cudaFuncSetAttribute(scores_kernel,
                         cudaFuncAttributeMaxDynamicSharedMemorySize, SMEM_TOTAL);

    dim3 gt(16, 16);
    transpose_split_kernel<<<gt, dim3(32, 8)>>>(Ua);
    decproj_kernel<<<BATCH, DDIM>>>(hid, Wa);
    dim3 g2(SLEN / 128, UDIM / 256, BATCH);
    scores_kernel<<<g2, 256, SMEM_TOTAL>>>(enc, Va);
    softmax_kernel<<<BATCH, 256>>>();
    dim3 g4(BATCH, 4);
    context_kernel<<<g4, 512>>>(enc);
    ctx_reduce_kernel<<<BATCH, 128>>>(out);
}